// round 6
// baseline (speedup 1.0000x reference)
#include <cuda_runtime.h>

#define NC  5
#define TPB 256
#define RPT 4   // rows per thread; 4 rows * 5 floats = 5 float4

__device__ __forceinline__ float fast_ex2(float x) {
    float y; asm("ex2.approx.f32 %0, %1;" : "=f"(y) : "f"(x)); return y;
}
__device__ __forceinline__ float fast_lg2(float x) {
    float y; asm("lg2.approx.f32 %0, %1;" : "=f"(y) : "f"(x)); return y;
}
__device__ __forceinline__ float fast_rcp(float x) {
    float y; asm("rcp.approx.f32 %0, %1;" : "=f"(y) : "f"(x)); return y;
}
__device__ __forceinline__ float fast_rsq(float x) {
    float y; asm("rsqrt.approx.f32 %0, %1;" : "=f"(y) : "f"(x)); return y;
}

// Constraint in log2 domain:
//   h(t)  = t*mu(t) - log2 Z(t) + C2,   C2 = (ln5 - eps)/ln2,  h increasing
//   h'(t) = ln2 * t * Var_p(log2 q),  p(t) = softmax(t ln q)
// Feasible (lam=0) iff h(1) <= 0.
#define C2CONST 2.1776498f     // (ln5 - 0.1)/ln2
#define LN2SQ   0.48045302f    // ln2^2
#define LN2CU   0.33302465f    // ln2^3
#define RLN2    1.44269504f    // 1/ln2
#define SQ2EPS  0.44721360f    // sqrt(2*eps) = sqrt(0.2)

__global__ void __launch_bounds__(TPB) kl_proj_kernel(
    const float* __restrict__ x,
    const float* __restrict__ W,
    const float* __restrict__ b,
    float* __restrict__ out,
    int n)
{
    __shared__ float sW[NC * NC];
    __shared__ float sb[NC];
    if (threadIdx.x < NC * NC) sW[threadIdx.x] = W[threadIdx.x];
    if (threadIdx.x < NC)      sb[threadIdx.x] = b[threadIdx.x];
    __syncthreads();

    int g = blockIdx.x * blockDim.x + threadIdx.x;   // thread handles rows [4g, 4g+4)
    if (g * RPT >= n) return;

    // ---- Coalesced vector load: 5 x float4 = 20 floats = 4 rows ----
    const float4* x4 = reinterpret_cast<const float4*>(x) + (size_t)g * 5;
    float a[RPT * NC];
    #pragma unroll
    for (int i = 0; i < 5; i++) {
        float4 v = x4[i];
        a[4*i+0] = v.x; a[4*i+1] = v.y; a[4*i+2] = v.z; a[4*i+3] = v.w;
    }

    float L[RPT][NC];
    float tc[RPT], lo[RPT], hi[RPT];
    bool  feas[RPT];

    // ---- Per row: linear, log2, feasibility, cubic init ----
    #pragma unroll
    for (int r = 0; r < RPT; r++) {
        float S1 = 0.f, A1 = 0.f;
        #pragma unroll
        for (int j = 0; j < NC; j++) {
            float q = sb[j];
            #pragma unroll
            for (int k = 0; k < NC; k++) q = fmaf(a[r*NC + k], sW[j*NC + k], q);
            float lj = fast_lg2(q);              // q in [0.1, 3.1]: safe
            L[r][j] = lj;
            S1 += q;
            A1 = fmaf(q, lj, A1);
        }
        float h1 = A1 * fast_rcp(S1) - fast_lg2(S1) + C2CONST;
        feas[r] = (h1 <= 0.f);

        // moments of L (log2) under uniform
        float s1 = 0.f, s2 = 0.f, s3 = 0.f;
        #pragma unroll
        for (int j = 0; j < NC; j++) {
            float lj = L[r][j];
            s1 += lj;
            s2 = fmaf(lj, lj, s2);
            s3 = fmaf(lj * lj, lj, s3);
        }
        float m  = s1 * 0.2f;
        float e2 = s2 * 0.2f;                    // E[L^2]
        float V2 = e2 - m * m;                   // Var (log2)
        float m3_2 = fmaf(s3, 0.2f, fmaf(-3.f * m, e2, 2.f * m * m * m));
        float V  = fmaxf(LN2SQ * V2, 1e-9f);     // nats
        float m3 = LN2CU * m3_2;                 // nats
        // cubic init: t = sqrt(2e / (V + (2/3) m3 t_lin)),  t_lin = sqrt(2e/V)
        float tl  = SQ2EPS * fast_rsq(V);
        float den = fmaxf(fmaf(0.6666667f * m3, tl, V), 1e-9f);
        float t0  = SQ2EPS * fast_rsq(den);
        tc[r] = fminf(0.95f, fmaxf(t0, 1e-4f));
        lo[r] = 0.f; hi[r] = 1.f;
    }

    // ---- 3 interleaved, safeguarded Newton iterations (4 indep chains) ----
    #pragma unroll
    for (int it = 0; it < 3; ++it) {
        #pragma unroll
        for (int r = 0; r < RPT; r++) {
            float t = tc[r];
            float S = 0.f, A = 0.f, B = 0.f;
            #pragma unroll
            for (int j = 0; j < NC; j++) {
                float e  = fast_ex2(t * L[r][j]);
                float el = e * L[r][j];
                S += e;
                A = fmaf(e,  L[r][j], A);
                B = fmaf(el, L[r][j], B);
            }
            float rr = fast_rcp(S);
            float mu = A * rr;
            float v  = fmaf(B, rr, -(mu * mu));
            float h  = fmaf(t, mu, C2CONST - fast_lg2(S));
            float hp = t * v;

            bool pos = (h > 0.f);
            hi[r] = pos ? t : hi[r];
            lo[r] = pos ? lo[r] : t;
            float tn = fmaf(-h * RLN2, fast_rcp(hp), t);   // tn = t - (h/ln2)/(t v)
            bool ok = (tn > lo[r]) && (tn < hi[r]);        // false also on NaN
            tc[r] = ok ? tn : 0.5f * (lo[r] + hi[r]);
        }
    }

    // ---- Final softmax per row + coalesced vector store ----
    float o[RPT * NC];
    #pragma unroll
    for (int r = 0; r < RPT; r++) {
        float t = feas[r] ? 1.f : tc[r];
        float e[NC], S = 0.f;
        #pragma unroll
        for (int j = 0; j < NC; j++) { e[j] = fast_ex2(t * L[r][j]); S += e[j]; }
        float rr = fast_rcp(S);
        #pragma unroll
        for (int j = 0; j < NC; j++) o[r*NC + j] = e[j] * rr;
    }

    float4* o4 = reinterpret_cast<float4*>(out) + (size_t)g * 5;
    #pragma unroll
    for (int i = 0; i < 5; i++)
        o4[i] = make_float4(o[4*i+0], o[4*i+1], o[4*i+2], o[4*i+3]);
}

extern "C" void kernel_launch(void* const* d_in, const int* in_sizes, int n_in,
                              void* d_out, int out_size) {
    const float* x = (const float*)d_in[0];
    const float* W = (const float*)d_in[1];
    const float* b = (const float*)d_in[2];
    float* out = (float*)d_out;
    int n = in_sizes[0] / NC;                 // 2,097,152 rows (divisible by 4)
    int threads = n / RPT;
    int blocks = (threads + TPB - 1) / TPB;
    kl_proj_kernel<<<blocks, TPB>>>(x, W, b, out, n);
}

// round 7
// speedup vs baseline: 1.7129x; 1.7129x over previous
#include <cuda_runtime.h>

#define NC 5
#define TPB 256

__device__ __forceinline__ float fast_ex2(float x) {
    float y; asm("ex2.approx.f32 %0, %1;" : "=f"(y) : "f"(x)); return y;
}
__device__ __forceinline__ float fast_lg2(float x) {
    float y; asm("lg2.approx.f32 %0, %1;" : "=f"(y) : "f"(x)); return y;
}
__device__ __forceinline__ float fast_rcp(float x) {
    float y; asm("rcp.approx.f32 %0, %1;" : "=f"(y) : "f"(x)); return y;
}
__device__ __forceinline__ float fast_rsq(float x) {
    float y; asm("rsqrt.approx.f32 %0, %1;" : "=f"(y) : "f"(x)); return y;
}

// Constraint in log2 domain:
//   h(t)  = t*mu(t) - log2 Z(t) + C2,   C2 = (ln5 - eps)/ln2,  h increasing
//   h'(t) = ln2 * t * Var_p(log2 q),  p(t) = softmax(t ln q)
// Feasible (lam=0) iff h(1) <= 0.
#define C2CONST 2.1776498f     // (ln5 - 0.1)/ln2
#define LN2SQ   0.48045302f    // ln2^2
#define LN2CU   0.33302465f    // ln2^3
#define RLN2    1.44269504f    // 1/ln2
#define SQ2EPS  0.44721360f    // sqrt(2*eps) = sqrt(0.2)

__global__ void __launch_bounds__(TPB) kl_proj_kernel(
    const float* __restrict__ x,
    const float* __restrict__ W,
    const float* __restrict__ b,
    float* __restrict__ out,
    int n)
{
    __shared__ float sW[NC * NC];
    __shared__ float sb[NC];
    if (threadIdx.x < NC * NC) sW[threadIdx.x] = W[threadIdx.x];
    if (threadIdx.x < NC)      sb[threadIdx.x] = b[threadIdx.x];
    __syncthreads();

    int row = blockIdx.x * blockDim.x + threadIdx.x;
    if (row >= n) return;

    // q = x @ W^T + b; q in [0.1, 3.1] by construction -> no max-shift anywhere.
    float xv[NC];
    #pragma unroll
    for (int k = 0; k < NC; k++) xv[k] = x[row * NC + k];

    // Linear + log, feasibility accumulators fused (q transient).
    float L[NC];
    float S1 = 0.f, A1 = 0.f;
    #pragma unroll
    for (int j = 0; j < NC; j++) {
        float q = sb[j];
        #pragma unroll
        for (int k = 0; k < NC; k++) q = fmaf(xv[k], sW[j * NC + k], q);
        float lj = fast_lg2(q);
        L[j] = lj;
        S1 += q;
        A1 = fmaf(q, lj, A1);
    }

    // Feasibility at t = 1: h(1) = E_p[log2 q] - log2(sum q) + C2
    float h1 = A1 * fast_rcp(S1) - fast_lg2(S1) + C2CONST;
    bool feas = (h1 <= 0.f);

    float t = 1.f;
    if (!__all_sync(0xffffffffu, feas)) {
        // Cubic init: KL(t) = (V/2)t^2 + (m3/3)t^3 + O(t^4) (nats, uniform wts)
        //   t0 = sqrt(2e / (V + (2/3) m3 * t_lin)),  t_lin = sqrt(2e/V)
        float s1 = 0.f, s2 = 0.f, s3 = 0.f;
        #pragma unroll
        for (int j = 0; j < NC; j++) {
            float lj = L[j];
            s1 += lj;
            s2 = fmaf(lj, lj, s2);
            s3 = fmaf(lj * lj, lj, s3);
        }
        float m   = s1 * 0.2f;
        float e2  = s2 * 0.2f;                          // E[L^2] (log2)
        float V   = fmaxf(LN2SQ * (e2 - m * m), 1e-9f); // Var, nats
        float m3  = LN2CU * fmaf(s3, 0.2f, fmaf(-3.f * m, e2, 2.f * m * m * m));
        float tl  = SQ2EPS * fast_rsq(V);
        float den = fmaxf(fmaf(0.6666667f * m3, tl, V), 1e-9f);
        float t0  = SQ2EPS * fast_rsq(den);
        t0 = fminf(0.95f, fmaxf(t0, 1e-4f));

        float lo = 0.f, hi = 1.f;
        float tc = t0;
        // 3 safeguarded Newton iterations, fully unrolled.
        #pragma unroll
        for (int it = 0; it < 3; ++it) {
            float S = 0.f, A = 0.f, B = 0.f;
            #pragma unroll
            for (int j = 0; j < NC; j++) {
                float e  = fast_ex2(tc * L[j]);
                float el = e * L[j];
                S += e;
                A = fmaf(e,  L[j], A);
                B = fmaf(el, L[j], B);
            }
            float r  = fast_rcp(S);
            float mu = A * r;
            float v  = fmaf(B, r, -(mu * mu));
            float h  = fmaf(tc, mu, C2CONST - fast_lg2(S));
            float hp = tc * v;

            bool pos = (h > 0.f);
            hi = pos ? tc : hi;
            lo = pos ? lo : tc;
            // Newton: tn = tc - (h/ln2) / (tc * v)
            float tn = fmaf(-h * RLN2, fast_rcp(hp), tc);
            bool ok = (tn > lo) && (tn < hi);   // false also on NaN
            tc = ok ? tn : 0.5f * (lo + hi);
        }
        t = feas ? 1.f : tc;
    }

    // Final p = softmax(t * log2 q) (exponents bounded; no shift).
    float e[NC], S = 0.f;
    #pragma unroll
    for (int j = 0; j < NC; j++) { e[j] = fast_ex2(t * L[j]); S += e[j]; }
    float r = fast_rcp(S);
    #pragma unroll
    for (int j = 0; j < NC; j++) out[row * NC + j] = e[j] * r;
}

extern "C" void kernel_launch(void* const* d_in, const int* in_sizes, int n_in,
                              void* d_out, int out_size) {
    const float* x = (const float*)d_in[0];
    const float* W = (const float*)d_in[1];
    const float* b = (const float*)d_in[2];
    float* out = (float*)d_out;
    int n = in_sizes[0] / NC;
    int blocks = (n + TPB - 1) / TPB;
    kl_proj_kernel<<<blocks, TPB>>>(x, W, b, out, n);
}